// round 2
// baseline (speedup 1.0000x reference)
#include <cuda_runtime.h>
#include <cuda_bf16.h>
#include <math.h>

// ---------------------------------------------------------------------------
// SemanticConsistencyLoss — per-class centers + Frobenius norm of difference.
// R2: latency-oriented rework of the histogram kernel.
//   * 2 CTAs per SM (channel halves), 16 warps/SM (4 per SMSP).
//   * Within a CTA: 256 threads, 2 threads per channel split by label range
//     ([0,75) vs [75,150)); range test is warp-uniform -> cheap skip.
//   * 64-pixel tiles, LDS.128 row reads into registers (TLSTR=68:
//     conflict-free per 8-lane phase, 16B aligned), register prefetch of the
//     next global tile (8x LDG.128 per thread).
//   * Partials -> __device__ scratch; unrolled reduce; warp-shuffle final.
// ---------------------------------------------------------------------------

#define NUM_CLASSES 150
#define CH          256
#define HALF_CH     128
#define NPIX        (512 * 512)
#define CHUNKS      74
#define PPC         3584          // 74*3584 >= NPIX, multiple of 64
#define TPB         256
#define TSTR        151           // table row stride (151 mod 32 = 23, odd)
#define TLSTR       68            // tile row stride (words): 16B aligned, phase-conflict-free
#define TILE        64
#define NTILES_MAX  (PPC / TILE)  // 56

__device__ float g_psums[2][CHUNKS][NUM_CLASSES][CH];  // ~22.7 MB scratch
__device__ float g_pcnts[2][CHUNKS][NUM_CLASSES];
__device__ float g_csq[NUM_CLASSES];

// smem (floats): table[128*151] | tile[128*68] | lbl[64 ints] | cnt[152]
#define SMEM_FLOATS (HALF_CH * TSTR + HALF_CH * TLSTR + 64 + 152)
#define SMEM_BYTES  (SMEM_FLOATS * 4)   // 112,992 B -> 2 CTAs/SM

__global__ void __launch_bounds__(TPB, 2)
accum_kernel(const float* __restrict__ src, const float* __restrict__ trg,
             const int* __restrict__ slab, const int* __restrict__ tlab) {
    extern __shared__ float sm[];
    float* table = sm;                            // HALF_CH * TSTR
    float* tile  = sm + HALF_CH * TSTR;           // HALF_CH * TLSTR
    int*   lbl   = (int*)(tile + HALF_CH * TLSTR);// 64
    float* cnt   = (float*)(lbl + 64);            // 152

    const int chunk = blockIdx.x;
    const int tsel  = blockIdx.y;
    const int chalf = blockIdx.z;
    const float* __restrict__ F =
        (tsel ? trg : src) + (size_t)chalf * HALF_CH * NPIX;
    const int* __restrict__ L = tsel ? tlab : slab;

    const int tid = threadIdx.x;
    const int c   = tid & (HALF_CH - 1);   // owned channel (within half)
    const int h   = tid >> 7;              // 0: labels [0,75)  1: labels [75,150)

    for (int i = tid; i < HALF_CH * TSTR; i += TPB) table[i] = 0.0f;
    if (tid < NUM_CLASSES) cnt[tid] = 0.0f;
    __syncthreads();

    const int pbase  = chunk * PPC;
    const int ntiles = min(NTILES_MAX, (NPIX - pbase) / TILE);  // 56 or 8

    float4 r[8];
    int lblreg = 0;

    // prefetch tile 0: q = tid + 256*i -> channel q>>4, pixel-quad q&15 (coalesced)
    {
        const int p0 = pbase;
#pragma unroll
        for (int i = 0; i < 8; ++i) {
            int q = tid + TPB * i;
            int cc = q >> 4, j4 = q & 15;
            r[i] = *(const float4*)(F + (size_t)cc * NPIX + p0 + j4 * 4);
        }
        if (tid < TILE) lblreg = L[p0 + tid];
    }

    float*       tab      = table + c * TSTR;
    const float* trowbase = tile + c * TLSTR;

    for (int ti = 0; ti < ntiles; ++ti) {
        // ---- stage registers -> transposed smem tile ----
#pragma unroll
        for (int i = 0; i < 8; ++i) {
            int q = tid + TPB * i;
            int cc = q >> 4, j4 = q & 15;
            *(float4*)(tile + cc * TLSTR + j4 * 4) = r[i];
        }
        if (tid < TILE) {
            lbl[tid] = lblreg;
            if (chalf == 0) atomicAdd(&cnt[lblreg], 1.0f);  // integer-exact
        }
        __syncthreads();

        // ---- prefetch next tile (fills DRAM pipe during accumulate) ----
        if (ti + 1 < ntiles) {
            const int p0 = pbase + (ti + 1) * TILE;
#pragma unroll
            for (int i = 0; i < 8; ++i) {
                int q = tid + TPB * i;
                int cc = q >> 4, j4 = q & 15;
                r[i] = *(const float4*)(F + (size_t)cc * NPIX + p0 + j4 * 4);
            }
            if (tid < TILE) lblreg = L[p0 + tid];
        }

        // ---- accumulate: vector row reads, label-range-split RMW ----
#pragma unroll
        for (int sub = 0; sub < 2; ++sub) {
            float4 x[8];
#pragma unroll
            for (int i = 0; i < 8; ++i)
                x[i] = *(const float4*)(trowbase + sub * 32 + i * 4);
            const int* lb = lbl + sub * 32;
#pragma unroll
            for (int j = 0; j < 32; ++j) {
                int lab = lb[j];
                bool mine = (lab < 75) == (h == 0);   // warp-uniform
                if (mine) {
                    float v = ((j & 3) == 0) ? x[j >> 2].x :
                              ((j & 3) == 1) ? x[j >> 2].y :
                              ((j & 3) == 2) ? x[j >> 2].z : x[j >> 2].w;
                    tab[lab] += v;
                }
            }
        }
        __syncthreads();
    }

    // ---- write partials [class][channel] (this CTA's 128-channel slice) ----
    float* outS = &g_psums[tsel][chunk][0][0] + chalf * HALF_CH;
    for (int i = tid; i < NUM_CLASSES * HALF_CH; i += TPB) {
        int cls = i >> 7;
        int ch  = i & (HALF_CH - 1);
        outS[cls * CH + ch] = table[ch * TSTR + cls];
    }
    if (chalf == 0 && tid < NUM_CLASSES)
        g_pcnts[tsel][chunk][tid] = cnt[tid];
}

__global__ void reduce_kernel() {
    const int cidx = blockIdx.x;    // class
    const int ch   = threadIdx.x;   // channel

    float ss = 0.0f, st = 0.0f;
#pragma unroll
    for (int k = 0; k < CHUNKS; ++k) {
        ss += g_psums[0][k][cidx][ch];
        st += g_psums[1][k][cidx][ch];
    }
    float cs = 0.0f, ctn = 0.0f;
#pragma unroll
    for (int k = 0; k < CHUNKS; ++k) {
        cs  += g_pcnts[0][k][cidx];
        ctn += g_pcnts[1][k][cidx];
    }
    float d = ss / (cs + 1e-8f) - st / (ctn + 1e-8f);

    __shared__ float red[CH];
    red[ch] = d * d;
    __syncthreads();
#pragma unroll
    for (int s = CH / 2; s > 0; s >>= 1) {
        if (ch < s) red[ch] += red[ch + s];
        __syncthreads();
    }
    if (ch == 0) g_csq[cidx] = red[0];
}

__global__ void final_kernel(float* out) {
    const int l = threadIdx.x;
    float s = 0.0f;
#pragma unroll
    for (int i = l; i < NUM_CLASSES; i += 32) s += g_csq[i];
#pragma unroll
    for (int o = 16; o > 0; o >>= 1) s += __shfl_down_sync(0xffffffffu, s, o);
    if (l == 0) out[0] = sqrtf(s);
}

extern "C" void kernel_launch(void* const* d_in, const int* in_sizes, int n_in,
                              void* d_out, int out_size) {
    const float* src = (const float*)d_in[0];   // src_fea  [1,256,512,512] f32
    const float* trg = (const float*)d_in[1];   // trg_fea
    const int*   sl  = (const int*)d_in[2];     // src_labels [1,512,512] i32
    const int*   tl  = (const int*)d_in[3];     // trg_pseudo_labels
    float* out = (float*)d_out;

    cudaFuncSetAttribute(accum_kernel,
                         cudaFuncAttributeMaxDynamicSharedMemorySize,
                         SMEM_BYTES);

    dim3 grid(CHUNKS, 2, 2);   // chunks x tensor x channel-half = 296 CTAs
    accum_kernel<<<grid, TPB, SMEM_BYTES>>>(src, trg, sl, tl);
    reduce_kernel<<<NUM_CLASSES, CH>>>();
    final_kernel<<<1, 32>>>(out);
}

// round 4
// speedup vs baseline: 1.3204x; 1.3204x over previous
#include <cuda_runtime.h>
#include <cuda_bf16.h>
#include <math.h>
#include <stdint.h>

// ---------------------------------------------------------------------------
// SemanticConsistencyLoss — per-class centers + Frobenius norm.
// R4: float4 smem-table RMW (4 channels per chain step), 4 label-streams
//     (lab&3) for race-free pixel parallelism, ballot masks + ffs iteration,
//     XOR-swizzled [pixel][channel] tile, register prefetch, one-wave grid.
// ---------------------------------------------------------------------------

#define NUM_CLASSES 150
#define CH        256
#define NPIX      (512 * 512)
#define CHUNKS    74
#define PPC       3584            // 74*3584 >= NPIX, multiple of 64
#define TILE      64
#define NT_MAX    (PPC / TILE)    // 56
#define TPB       256

__device__ float g_psums[2][CHUNKS][NUM_CLASSES][CH];  // ~22.7 MB scratch
__device__ float g_pcnts[2][CHUNKS][NUM_CLASSES];
__device__ float g_csq[NUM_CLASSES];

// smem (float indices): table[150*256] | tile[64*256] | lbl[64] | mask[8] | cnt[152]
#define SM_TILE   (NUM_CLASSES * CH)          // 38400
#define SM_LBL    (SM_TILE + TILE * CH)       // +16384
#define SM_MASK   (SM_LBL + 64)
#define SM_CNT    (SM_MASK + 8)
#define SMEM_FLOATS (SM_CNT + 152)
#define SMEM_BYTES  (SMEM_FLOATS * 4)         // 220,032 B (< 227 KB cap)

__global__ void __launch_bounds__(TPB, 1)
accum_kernel(const float* __restrict__ src, const float* __restrict__ trg,
             const int* __restrict__ slab, const int* __restrict__ tlab) {
    extern __shared__ float smf[];
    float*    table = smf;                 // [class][256ch], no pad
    float*    tile  = smf + SM_TILE;       // [64px][256ch], XOR-quad swizzle
    int*      lbl   = (int*)(smf + SM_LBL);
    unsigned* maskp = (unsigned*)(smf + SM_MASK);  // [stream][half]
    int*      cnt   = (int*)(smf + SM_CNT);

    const int chunk = blockIdx.x;
    const int tsel  = blockIdx.y;
    const float* __restrict__ F = tsel ? trg : src;
    const int*   __restrict__ L = tsel ? tlab : slab;

    const int tid  = threadIdx.x;
    const int lane = tid & 31;
    const int q    = tid & 63;    // channel quad (channels 4q..4q+3)
    const int s    = tid >> 6;    // label stream: handles lab&3 == s (warp-uniform)

    // zero table + counters
    for (int i = tid; i < NUM_CLASSES * CH; i += TPB) table[i] = 0.0f;
    if (tid < NUM_CLASSES) cnt[tid] = 0;
    __syncthreads();

    const int pbase  = chunk * PPC;
    const int ntiles = min(NT_MAX, (NPIX - pbase) / TILE);  // 56 or 8

    // ---- register prefetch of tile 0 ----
    // q16 = tid + 256*i : channel = q16>>4, 16B-column c16 = q16&15
    float4 r[16];
    int labreg = 0;
    {
#pragma unroll
        for (int i = 0; i < 16; ++i) {
            int q16 = tid + TPB * i;
            int ch  = q16 >> 4, c16 = q16 & 15;
            r[i] = *(const float4*)(F + (size_t)ch * NPIX + pbase + c16 * 4);
        }
        if (tid < TILE) labreg = L[pbase + tid];
    }

    for (int t = 0; t < ntiles; ++t) {
        // ---- stage: regs -> swizzled [px][ch] tile ----
        // element (j = 4*c16 + k, ch): word = j*256 + 4*((ch>>2) ^ c16) + (ch&3)
#pragma unroll
        for (int i = 0; i < 16; ++i) {
            int q16 = tid + TPB * i;
            int ch  = q16 >> 4, c16 = q16 & 15;
            int sw  = ((ch >> 2) ^ c16);
            float* d = tile + (4 * c16) * CH + 4 * sw + (ch & 3);
            d[0]       = r[i].x;
            d[CH]      = r[i].y;
            d[2 * CH]  = r[i].z;
            d[3 * CH]  = r[i].w;
        }
        // ---- labels, counts, per-stream ballot masks ----
        if (tid < TILE) {   // warps 0,1 fully active
            lbl[tid] = labreg;
            atomicAdd(&cnt[labreg], 1);     // integer-exact
            int w  = tid >> 5;
            int r3 = labreg & 3;
#pragma unroll
            for (int ss = 0; ss < 4; ++ss) {
                unsigned b = __ballot_sync(0xffffffffu, r3 == ss);
                if (lane == ss) maskp[ss * 2 + w] = b;
            }
        }
        __syncthreads();

        // ---- prefetch next tile (fills DRAM pipe under the accumulate) ----
        if (t + 1 < ntiles) {
            const int p0 = pbase + (t + 1) * TILE;
#pragma unroll
            for (int i = 0; i < 16; ++i) {
                int q16 = tid + TPB * i;
                int ch  = q16 >> 4, c16 = q16 & 15;
                r[i] = *(const float4*)(F + (size_t)ch * NPIX + p0 + c16 * 4);
            }
            if (tid < TILE) labreg = L[p0 + tid];
        }

        // ---- accumulate: stream s visits only its pixels via ffs over mask ----
        // float4 RMW: 4 channels per chain step; streams are label-disjoint.
#pragma unroll
        for (int h = 0; h < 2; ++h) {
            unsigned m = maskp[s * 2 + h];   // warp-uniform
            while (m) {
                int j = __ffs(m) - 1;
                m &= m - 1;
                int jj  = h * 32 + j;
                int lab = lbl[jj];
                const float4 x =
                    *(const float4*)(tile + jj * CH + 4 * (q ^ (jj >> 2)));
                float4* tp = (float4*)(table + lab * CH + 4 * q);
                float4 v = *tp;
                v.x += x.x; v.y += x.y; v.z += x.z; v.w += x.w;
                *tp = v;
            }
        }
        __syncthreads();
    }

    // ---- epilogue: table -> partial scratch (coalesced) ----
    for (int c = 0; c < NUM_CLASSES; ++c)
        g_psums[tsel][chunk][c][tid] = table[c * CH + tid];
    if (tid < NUM_CLASSES)
        g_pcnts[tsel][chunk][tid] = (float)cnt[tid];
}

__global__ void reduce_kernel() {
    const int cidx = blockIdx.x;    // class
    const int ch   = threadIdx.x;   // channel

    float ss = 0.0f, st = 0.0f;
#pragma unroll
    for (int k = 0; k < CHUNKS; ++k) {
        ss += g_psums[0][k][cidx][ch];
        st += g_psums[1][k][cidx][ch];
    }
    float cs = 0.0f, ctn = 0.0f;
#pragma unroll
    for (int k = 0; k < CHUNKS; ++k) {
        cs  += g_pcnts[0][k][cidx];
        ctn += g_pcnts[1][k][cidx];
    }
    float d = ss / (cs + 1e-8f) - st / (ctn + 1e-8f);

    __shared__ float red[CH];
    red[ch] = d * d;
    __syncthreads();
#pragma unroll
    for (int s = CH / 2; s > 0; s >>= 1) {
        if (ch < s) red[ch] += red[ch + s];
        __syncthreads();
    }
    if (ch == 0) g_csq[cidx] = red[0];
}

__global__ void final_kernel(float* out) {
    const int l = threadIdx.x;
    float s = 0.0f;
#pragma unroll
    for (int i = l; i < NUM_CLASSES; i += 32) s += g_csq[i];
#pragma unroll
    for (int o = 16; o > 0; o >>= 1) s += __shfl_down_sync(0xffffffffu, s, o);
    if (l == 0) out[0] = sqrtf(s);
}

extern "C" void kernel_launch(void* const* d_in, const int* in_sizes, int n_in,
                              void* d_out, int out_size) {
    const float* src = (const float*)d_in[0];   // src_fea  [1,256,512,512] f32
    const float* trg = (const float*)d_in[1];   // trg_fea
    const int*   sl  = (const int*)d_in[2];     // src_labels [1,512,512] i32
    const int*   tl  = (const int*)d_in[3];     // trg_pseudo_labels
    float* out = (float*)d_out;

    cudaFuncSetAttribute(accum_kernel,
                         cudaFuncAttributeMaxDynamicSharedMemorySize,
                         SMEM_BYTES);

    dim3 grid(CHUNKS, 2);   // 148 CTAs = one wave, 1 CTA/SM
    accum_kernel<<<grid, TPB, SMEM_BYTES>>>(src, trg, sl, tl);
    reduce_kernel<<<NUM_CLASSES, CH>>>();
    final_kernel<<<1, 32>>>(out);
}

// round 5
// speedup vs baseline: 1.5462x; 1.1710x over previous
#include <cuda_runtime.h>
#include <cuda_bf16.h>
#include <math.h>
#include <stdint.h>

// ---------------------------------------------------------------------------
// SemanticConsistencyLoss — R5: barrier-free match-based accumulation.
//  warp = 16 channels; lanes = 32x2 pixels (float2 coalesced channel-major).
//  __match_any_sync resolves intra-warp label collisions via rank-rounds.
//  table[class][ch] smem, stride 257 (bank = lab + c, spread).
//  No smem staging tile, no CTA barriers in main loop, 16 warps/CTA,
//  double-buffered register prefetch (1 group = 64 px ahead).
// ---------------------------------------------------------------------------

#define NUM_CLASSES 150
#define CH        256
#define NPIX      (512 * 512)
#define CHUNKS    74
#define PPC       3584            // 74*3584 >= NPIX, multiple of 64
#define GPX       64              // pixels per group (32 lanes x float2)
#define TPB       512
#define NWARP     16
#define CPW       16              // channels per warp
#define STR       257             // table row stride (257 mod 32 = 1)

__device__ float g_psums[2][CHUNKS][NUM_CLASSES][CH];
__device__ float g_pcnts[2][CHUNKS][NUM_CLASSES];
__device__ float g_csq[NUM_CLASSES];

// smem floats: table[150*257] | lbl[PPC] | cnt[152]
#define SM_LBL      (NUM_CLASSES * STR)          // 38550
#define SM_CNT      (SM_LBL + PPC)
#define SMEM_FLOATS (SM_CNT + 152)
#define SMEM_BYTES  (SMEM_FLOATS * 4)            // ~169.5 KB

__global__ void __launch_bounds__(TPB, 1)
accum_kernel(const float* __restrict__ src, const float* __restrict__ trg,
             const int* __restrict__ slab, const int* __restrict__ tlab) {
    extern __shared__ float smf[];
    float* table = smf;
    int*   lbl_s = (int*)(smf + SM_LBL);
    int*   cnt   = (int*)(smf + SM_CNT);

    const int chunk = blockIdx.x;
    const int tsel  = blockIdx.y;
    const float* __restrict__ F = tsel ? trg : src;
    const int*   __restrict__ L = tsel ? tlab : slab;

    const int tid  = threadIdx.x;
    const int wid  = tid >> 5;
    const int lane = tid & 31;
    const int c0   = wid * CPW;          // this warp's 16 channels

    // ---- zero table + counters ----
    for (int i = tid; i < NUM_CLASSES * STR; i += TPB) table[i] = 0.0f;
    if (tid < NUM_CLASSES) cnt[tid] = 0;
    __syncthreads();

    const int pbase = chunk * PPC;
    const int psz   = min(PPC, NPIX - pbase);
    const int ng    = psz / GPX;         // 56 (last chunk: 8)

    // ---- cache labels + histogram (once per CTA) ----
    for (int i = tid; i < psz; i += TPB) {
        int l = L[pbase + i];
        lbl_s[i] = l;
        atomicAdd(&cnt[l], 1);           // integer-exact
    }
    __syncthreads();

    // ---- main loop: barrier-free, per-warp independent ----
    const float* Fb = F + pbase + 2 * lane;
    float2 v[2][CPW];
    int la, lb, lan = 0, lbn = 0;
#pragma unroll
    for (int i = 0; i < CPW; ++i)
        v[0][i] = *(const float2*)(Fb + (size_t)(c0 + i) * NPIX);
    la = lbl_s[2 * lane];
    lb = lbl_s[2 * lane + 1];

#pragma unroll 2
    for (int g = 0; g < ng; ++g) {
        const int cur = g & 1;

        // prefetch next group (fills DRAM pipe under the RMW below)
        if (g + 1 < ng) {
            const float* fp = Fb + (g + 1) * GPX;
#pragma unroll
            for (int i = 0; i < CPW; ++i)
                v[cur ^ 1][i] = *(const float2*)(fp + (size_t)(c0 + i) * NPIX);
            lan = lbl_s[(g + 1) * GPX + 2 * lane];
            lbn = lbl_s[(g + 1) * GPX + 2 * lane + 1];
        }

        // intra-warp collision ranks (labels identical across all 16 channels)
        unsigned ga = __match_any_sync(0xffffffffu, la);
        unsigned ra = __popc(ga & ((1u << lane) - 1u));
        unsigned gb = __match_any_sync(0xffffffffu, lb);
        unsigned rb = __popc(gb & ((1u << lane) - 1u));

        float* rowa = table + la * STR + c0;
        float* rowb = table + lb * STR + c0;

        // rank-round RMW: active lanes in a round have distinct labels ->
        // race-free; 16 independent scalar LDS/FADD/STS per lane pipeline well.
        for (unsigned r = 0; __any_sync(0xffffffffu, ra >= r); ++r) {
            if (ra == r) {
#pragma unroll
                for (int i = 0; i < CPW; ++i) rowa[i] += v[cur][i].x;
            }
            __syncwarp();
        }
        for (unsigned r = 0; __any_sync(0xffffffffu, rb >= r); ++r) {
            if (rb == r) {
#pragma unroll
                for (int i = 0; i < CPW; ++i) rowb[i] += v[cur][i].y;
            }
            __syncwarp();
        }
        la = lan; lb = lbn;
    }
    __syncthreads();

    // ---- epilogue: table -> partial scratch (coalesced) ----
    for (int i = tid; i < NUM_CLASSES * CH; i += TPB) {
        int cls = i >> 8, ch = i & 255;
        g_psums[tsel][chunk][cls][ch] = table[cls * STR + ch];
    }
    if (tid < NUM_CLASSES)
        g_pcnts[tsel][chunk][tid] = (float)cnt[tid];
}

__global__ void reduce_kernel() {
    const int cidx = blockIdx.x;    // class
    const int ch   = threadIdx.x;   // channel

    float ss = 0.0f, st = 0.0f;
#pragma unroll
    for (int k = 0; k < CHUNKS; ++k) {
        ss += g_psums[0][k][cidx][ch];
        st += g_psums[1][k][cidx][ch];
    }
    float cs = 0.0f, ctn = 0.0f;
#pragma unroll
    for (int k = 0; k < CHUNKS; ++k) {
        cs  += g_pcnts[0][k][cidx];
        ctn += g_pcnts[1][k][cidx];
    }
    float d = ss / (cs + 1e-8f) - st / (ctn + 1e-8f);

    __shared__ float red[CH];
    red[ch] = d * d;
    __syncthreads();
#pragma unroll
    for (int s = CH / 2; s > 0; s >>= 1) {
        if (ch < s) red[ch] += red[ch + s];
        __syncthreads();
    }
    if (ch == 0) g_csq[cidx] = red[0];
}

__global__ void final_kernel(float* out) {
    const int l = threadIdx.x;
    float s = 0.0f;
#pragma unroll
    for (int i = l; i < NUM_CLASSES; i += 32) s += g_csq[i];
#pragma unroll
    for (int o = 16; o > 0; o >>= 1) s += __shfl_down_sync(0xffffffffu, s, o);
    if (l == 0) out[0] = sqrtf(s);
}

extern "C" void kernel_launch(void* const* d_in, const int* in_sizes, int n_in,
                              void* d_out, int out_size) {
    const float* src = (const float*)d_in[0];   // src_fea  [1,256,512,512] f32
    const float* trg = (const float*)d_in[1];   // trg_fea
    const int*   sl  = (const int*)d_in[2];     // src_labels [1,512,512] i32
    const int*   tl  = (const int*)d_in[3];     // trg_pseudo_labels
    float* out = (float*)d_out;

    cudaFuncSetAttribute(accum_kernel,
                         cudaFuncAttributeMaxDynamicSharedMemorySize,
                         SMEM_BYTES);

    dim3 grid(CHUNKS, 2);   // 148 CTAs = one wave
    accum_kernel<<<grid, TPB, SMEM_BYTES>>>(src, trg, sl, tl);
    reduce_kernel<<<NUM_CLASSES, CH>>>();
    final_kernel<<<1, 32>>>(out);
}

// round 6
// speedup vs baseline: 1.6621x; 1.0750x over previous
#include <cuda_runtime.h>
#include <cuda_bf16.h>
#include <math.h>
#include <stdint.h>

// ---------------------------------------------------------------------------
// SemanticConsistencyLoss — R6: pixel-per-warp conflict-free RMW.
//  * warp w owns labels with (lab & 15) == w  -> no cross-warp races.
//  * per pixel: full warp updates 256 channels (lane = channel slice):
//      table bank = lane  -> conflict-free LDS/FADD/STS.
//  * staging tile [256ch][33px-stride] scalar stores/reads, all bank-perfect.
//  * one __syncthreads per 32-px tile, double-buffered tiles, register
//    prefetch of next tile's global loads during the RMW phase.
// ---------------------------------------------------------------------------

#define NUM_CLASSES 150
#define CH        256
#define NPIX      (512 * 512)
#define CHUNKS    74
#define PPC       3584            // 74*3584 >= NPIX, multiple of 32
#define TPX       32              // pixels per tile
#define TPB       512
#define TSTRIDE   33              // tile px-stride (odd -> bank rotation)
#define TILE_W    (CH * TSTRIDE)  // 8448 words per tile buffer

__device__ float g_psums[2][CHUNKS][NUM_CLASSES][CH];
__device__ float g_pcnts[2][CHUNKS][NUM_CLASSES];
__device__ float g_csq[NUM_CLASSES];

// smem floats: table[150*256] | tile[2][8448] | cnt[152]
#define SM_TILE     (NUM_CLASSES * CH)              // 38400
#define SM_CNT      (SM_TILE + 2 * TILE_W)          // +16896
#define SMEM_FLOATS (SM_CNT + 152)
#define SMEM_BYTES  (SMEM_FLOATS * 4)               // 221,792 B

__global__ void __launch_bounds__(TPB, 1)
accum_kernel(const float* __restrict__ src, const float* __restrict__ trg,
             const int* __restrict__ slab, const int* __restrict__ tlab) {
    extern __shared__ float smf[];
    float* table = smf;                 // [class][256], bank = ch&31
    float* tiles = smf + SM_TILE;       // [2][256][33]
    int*   cnt   = (int*)(smf + SM_CNT);

    const int chunk = blockIdx.x;
    const int tsel  = blockIdx.y;
    const float* __restrict__ F = tsel ? trg : src;
    const int*   __restrict__ L = tsel ? tlab : slab;

    const int tid  = threadIdx.x;
    const int wid  = tid >> 5;          // 0..15: owns labels lab&15==wid
    const int lane = tid & 31;

    // zero table + counters
    for (int i = tid; i < NUM_CLASSES * CH; i += TPB) table[i] = 0.0f;
    if (tid < NUM_CLASSES) cnt[tid] = 0;
    __syncthreads();

    const int pbase  = chunk * PPC;
    const int psz    = min(PPC, NPIX - pbase);
    const int ntiles = psz / TPX;       // 112 (last chunk: 16)

    // ---- per-CTA label histogram (integer-exact) ----
    for (int i = tid; i < psz; i += TPB)
        atomicAdd(&cnt[L[pbase + i]], 1);
    __syncthreads();

    // ---- register prefetch of tile 0 ----
    // q = tid + 512*i (i<4): ch = q>>3, p4 = q&7 (4 px per float4) -> coalesced
    float4 r[4];
    int mylbl;
    {
#pragma unroll
        for (int i = 0; i < 4; ++i) {
            int q = tid + TPB * i;
            int ch = q >> 3, p4 = q & 7;
            r[i] = *(const float4*)(F + (size_t)ch * NPIX + pbase + p4 * 4);
        }
        mylbl = L[pbase + lane];        // lane <-> pixel-in-tile
    }

    for (int t = 0; t < ntiles; ++t) {
        float* tb = tiles + (t & 1) * TILE_W;

        // ---- stage: scalar stores, bank = (ch + 4*p4 + k) & 31 (distinct) ----
#pragma unroll
        for (int i = 0; i < 4; ++i) {
            int q = tid + TPB * i;
            int ch = q >> 3, p4 = q & 7;
            float* d = tb + ch * TSTRIDE + p4 * 4;
            d[0] = r[i].x; d[1] = r[i].y; d[2] = r[i].z; d[3] = r[i].w;
        }
        const int lblcur = mylbl;
        __syncthreads();   // single barrier per tile (safe: double buffer)

        // ---- prefetch next tile (LDG latency hidden under RMW) ----
        if (t + 1 < ntiles) {
            const int p0 = pbase + (t + 1) * TPX;
#pragma unroll
            for (int i = 0; i < 4; ++i) {
                int q = tid + TPB * i;
                int ch = q >> 3, p4 = q & 7;
                r[i] = *(const float4*)(F + (size_t)ch * NPIX + p0 + p4 * 4);
            }
            mylbl = L[p0 + lane];
        }

        // ---- RMW: warp wid handles pixels with lab&15==wid ----
        unsigned m = __ballot_sync(0xffffffffu, (lblcur & 15) == wid);
        while (m) {
            const int j = __ffs(m) - 1;
            m &= m - 1;
            const int row = __shfl_sync(0xffffffffu, lblcur, j);
            float*       trow = table + row * CH + lane;   // bank = lane
            const float* srcc = tb + lane * TSTRIDE + j;   // bank = (lane+j)&31
#pragma unroll
            for (int h = 0; h < 8; ++h)
                trow[h * 32] += srcc[h * 32 * TSTRIDE];
        }
    }
    __syncthreads();

    // ---- epilogue: table -> partial scratch (coalesced) ----
    for (int i = tid; i < NUM_CLASSES * CH; i += TPB) {
        int cls = i >> 8, ch = i & 255;
        g_psums[tsel][chunk][cls][ch] = table[cls * CH + ch];
    }
    if (tid < NUM_CLASSES)
        g_pcnts[tsel][chunk][tid] = (float)cnt[tid];
}

__global__ void reduce_kernel() {
    const int cidx = blockIdx.x;    // class
    const int ch   = threadIdx.x;   // channel

    float ss = 0.0f, st = 0.0f;
#pragma unroll
    for (int k = 0; k < CHUNKS; ++k) {
        ss += g_psums[0][k][cidx][ch];
        st += g_psums[1][k][cidx][ch];
    }
    float cs = 0.0f, ctn = 0.0f;
#pragma unroll
    for (int k = 0; k < CHUNKS; ++k) {
        cs  += g_pcnts[0][k][cidx];
        ctn += g_pcnts[1][k][cidx];
    }
    float d = ss / (cs + 1e-8f) - st / (ctn + 1e-8f);

    __shared__ float red[CH];
    red[ch] = d * d;
    __syncthreads();
#pragma unroll
    for (int s = CH / 2; s > 0; s >>= 1) {
        if (ch < s) red[ch] += red[ch + s];
        __syncthreads();
    }
    if (ch == 0) g_csq[cidx] = red[0];
}

__global__ void final_kernel(float* out) {
    const int l = threadIdx.x;
    float s = 0.0f;
#pragma unroll
    for (int i = l; i < NUM_CLASSES; i += 32) s += g_csq[i];
#pragma unroll
    for (int o = 16; o > 0; o >>= 1) s += __shfl_down_sync(0xffffffffu, s, o);
    if (l == 0) out[0] = sqrtf(s);
}

extern "C" void kernel_launch(void* const* d_in, const int* in_sizes, int n_in,
                              void* d_out, int out_size) {
    const float* src = (const float*)d_in[0];   // src_fea  [1,256,512,512] f32
    const float* trg = (const float*)d_in[1];   // trg_fea
    const int*   sl  = (const int*)d_in[2];     // src_labels [1,512,512] i32
    const int*   tl  = (const int*)d_in[3];     // trg_pseudo_labels
    float* out = (float*)d_out;

    cudaFuncSetAttribute(accum_kernel,
                         cudaFuncAttributeMaxDynamicSharedMemorySize,
                         SMEM_BYTES);

    dim3 grid(CHUNKS, 2);   // 148 CTAs = one wave
    accum_kernel<<<grid, TPB, SMEM_BYTES>>>(src, trg, sl, tl);
    reduce_kernel<<<NUM_CLASSES, CH>>>();
    final_kernel<<<1, 32>>>(out);
}

// round 7
// speedup vs baseline: 1.9310x; 1.1618x over previous
#include <cuda_runtime.h>
#include <cuda_bf16.h>
#include <math.h>
#include <stdint.h>

// ---------------------------------------------------------------------------
// SemanticConsistencyLoss — R7: R6's conflict-free pixel-per-warp RMW,
// channel-split 2x for occupancy 2 (32 warps/SM) to cover barrier/chain
// latency. Grid 74 x 2 tensors x 2 channel-halves = 296 CTAs = one wave.
//  * warp w owns labels with (lab & 15) == w  -> no cross-warp races.
//  * per pixel: warp updates its 128 channels (4 stride-32 slices):
//      table bank = lane -> conflict-free LDS/FADD/STS.
//  * staging tile [128ch][33px-stride], all accesses bank-perfect.
//  * one __syncthreads per 32-px tile, double-buffered, register prefetch.
// ---------------------------------------------------------------------------

#define NUM_CLASSES 150
#define CH        256
#define HCH       128             // channels per CTA
#define NPIX      (512 * 512)
#define CHUNKS    74
#define PPC       3584            // 74*3584 >= NPIX, multiple of 32
#define TPX       32              // pixels per tile
#define TPB       512
#define TSTRIDE   33              // tile px-stride (odd -> bank rotation)
#define TILE_W    (HCH * TSTRIDE) // 4224 words per tile buffer

__device__ float g_psums[2][CHUNKS][NUM_CLASSES][CH];
__device__ float g_pcnts[2][CHUNKS][NUM_CLASSES];
__device__ float g_csq[NUM_CLASSES];

// smem floats: table[150*128] | tile[2][4224] | cnt[152]
#define SM_TILE     (NUM_CLASSES * HCH)             // 19200
#define SM_CNT      (SM_TILE + 2 * TILE_W)          // +8448
#define SMEM_FLOATS (SM_CNT + 152)
#define SMEM_BYTES  (SMEM_FLOATS * 4)               // 111,200 B -> 2 CTAs/SM

__global__ void __launch_bounds__(TPB, 2)
accum_kernel(const float* __restrict__ src, const float* __restrict__ trg,
             const int* __restrict__ slab, const int* __restrict__ tlab) {
    extern __shared__ float smf[];
    float* table = smf;                 // [class][128], bank = ch&31
    float* tiles = smf + SM_TILE;       // [2][128][33]
    int*   cnt   = (int*)(smf + SM_CNT);

    const int chunk = blockIdx.x;
    const int tsel  = blockIdx.y;
    const int chalf = blockIdx.z;
    const float* __restrict__ F =
        (tsel ? trg : src) + (size_t)chalf * HCH * NPIX;
    const int*   __restrict__ L = tsel ? tlab : slab;

    const int tid  = threadIdx.x;
    const int wid  = tid >> 5;          // 0..15: owns labels lab&15==wid
    const int lane = tid & 31;

    // zero table + counters
    for (int i = tid; i < NUM_CLASSES * HCH; i += TPB) table[i] = 0.0f;
    if (tid < NUM_CLASSES) cnt[tid] = 0;
    __syncthreads();

    const int pbase  = chunk * PPC;
    const int psz    = min(PPC, NPIX - pbase);
    const int ntiles = psz / TPX;       // 112 (last chunk: 16)

    // ---- per-chunk label histogram (integer-exact, chalf 0 only) ----
    if (chalf == 0) {
        for (int i = tid; i < psz; i += TPB)
            atomicAdd(&cnt[L[pbase + i]], 1);
    }
    __syncthreads();

    // ---- register prefetch of tile 0 ----
    // q = tid + 512*i (i<2): ch = q>>3 (0..127), p4 = q&7 -> coalesced LDG.128
    float4 r[2];
    int mylbl;
    {
#pragma unroll
        for (int i = 0; i < 2; ++i) {
            int q = tid + TPB * i;
            int ch = q >> 3, p4 = q & 7;
            r[i] = *(const float4*)(F + (size_t)ch * NPIX + pbase + p4 * 4);
        }
        mylbl = L[pbase + lane];        // lane <-> pixel-in-tile
    }

    for (int t = 0; t < ntiles; ++t) {
        float* tb = tiles + (t & 1) * TILE_W;

        // ---- stage: scalar stores, bank = (ch + 4*p4 + k) & 31 (distinct) ----
#pragma unroll
        for (int i = 0; i < 2; ++i) {
            int q = tid + TPB * i;
            int ch = q >> 3, p4 = q & 7;
            float* d = tb + ch * TSTRIDE + p4 * 4;
            d[0] = r[i].x; d[1] = r[i].y; d[2] = r[i].z; d[3] = r[i].w;
        }
        const int lblcur = mylbl;
        __syncthreads();   // single barrier per tile (safe: double buffer)

        // ---- prefetch next tile (LDG latency hidden under RMW) ----
        if (t + 1 < ntiles) {
            const int p0 = pbase + (t + 1) * TPX;
#pragma unroll
            for (int i = 0; i < 2; ++i) {
                int q = tid + TPB * i;
                int ch = q >> 3, p4 = q & 7;
                r[i] = *(const float4*)(F + (size_t)ch * NPIX + p0 + p4 * 4);
            }
            mylbl = L[p0 + lane];
        }

        // ---- RMW: warp wid handles pixels with lab&15==wid ----
        unsigned m = __ballot_sync(0xffffffffu, (lblcur & 15) == wid);
        while (m) {
            const int j = __ffs(m) - 1;
            m &= m - 1;
            const int row = __shfl_sync(0xffffffffu, lblcur, j);
            float*       trow = table + row * HCH + lane;  // bank = lane
            const float* srcc = tb + lane * TSTRIDE + j;   // bank = (lane+j)&31
#pragma unroll
            for (int h = 0; h < 4; ++h)
                trow[h * 32] += srcc[h * 32 * TSTRIDE];
        }
    }
    __syncthreads();

    // ---- epilogue: table -> partial scratch (coalesced) ----
    for (int i = tid; i < NUM_CLASSES * HCH; i += TPB) {
        int cls = i >> 7, ch = i & 127;
        g_psums[tsel][chunk][cls][chalf * HCH + ch] = table[cls * HCH + ch];
    }
    if (chalf == 0 && tid < NUM_CLASSES)
        g_pcnts[tsel][chunk][tid] = (float)cnt[tid];
}

__global__ void reduce_kernel() {
    const int cidx = blockIdx.x;    // class
    const int ch   = threadIdx.x;   // channel

    float ss = 0.0f, st = 0.0f;
#pragma unroll
    for (int k = 0; k < CHUNKS; ++k) {
        ss += g_psums[0][k][cidx][ch];
        st += g_psums[1][k][cidx][ch];
    }
    float cs = 0.0f, ctn = 0.0f;
#pragma unroll
    for (int k = 0; k < CHUNKS; ++k) {
        cs  += g_pcnts[0][k][cidx];
        ctn += g_pcnts[1][k][cidx];
    }
    float d = ss / (cs + 1e-8f) - st / (ctn + 1e-8f);

    __shared__ float red[CH];
    red[ch] = d * d;
    __syncthreads();
#pragma unroll
    for (int s = CH / 2; s > 0; s >>= 1) {
        if (ch < s) red[ch] += red[ch + s];
        __syncthreads();
    }
    if (ch == 0) g_csq[cidx] = red[0];
}

__global__ void final_kernel(float* out) {
    const int l = threadIdx.x;
    float s = 0.0f;
#pragma unroll
    for (int i = l; i < NUM_CLASSES; i += 32) s += g_csq[i];
#pragma unroll
    for (int o = 16; o > 0; o >>= 1) s += __shfl_down_sync(0xffffffffu, s, o);
    if (l == 0) out[0] = sqrtf(s);
}

extern "C" void kernel_launch(void* const* d_in, const int* in_sizes, int n_in,
                              void* d_out, int out_size) {
    const float* src = (const float*)d_in[0];   // src_fea  [1,256,512,512] f32
    const float* trg = (const float*)d_in[1];   // trg_fea
    const int*   sl  = (const int*)d_in[2];     // src_labels [1,512,512] i32
    const int*   tl  = (const int*)d_in[3];     // trg_pseudo_labels
    float* out = (float*)d_out;

    cudaFuncSetAttribute(accum_kernel,
                         cudaFuncAttributeMaxDynamicSharedMemorySize,
                         SMEM_BYTES);

    dim3 grid(CHUNKS, 2, 2);   // 296 CTAs = one wave at occ 2
    accum_kernel<<<grid, TPB, SMEM_BYTES>>>(src, trg, sl, tl);
    reduce_kernel<<<NUM_CLASSES, CH>>>();
    final_kernel<<<1, 32>>>(out);
}

// round 8
// speedup vs baseline: 2.0751x; 1.0746x over previous
#include <cuda_runtime.h>
#include <cuda_bf16.h>
#include <math.h>
#include <stdint.h>

// ---------------------------------------------------------------------------
// SemanticConsistencyLoss — R8: register-resident class accumulators.
//  * warp w owns labels {lab : lab&15 == w} = {16k+w, k<10}  -> no races.
//  * thread keeps float4 acc[10]: (class k, channels lane+{0,32,64,96}).
//  * per pixel: 4 conflict-free tile LDS + warp-uniform switch(k) + 4 FADD.
//    NO smem table -> crossbar traffic halved vs R7 (2 words/elem): DRAM-bound.
//  * staging tile [128ch][33px] as R7 (bank-perfect), double-buffered,
//    register prefetch, one barrier per 32-px tile, occ 2 (32 warps/SM).
// ---------------------------------------------------------------------------

#define NUM_CLASSES 150
#define CH        256
#define HCH       128             // channels per CTA
#define NPIX      (512 * 512)
#define CHUNKS    74
#define PPC       3584            // 74*3584 >= NPIX, multiple of 32
#define TPX       32              // pixels per tile
#define TPB       512
#define TSTRIDE   33
#define TILE_W    (HCH * TSTRIDE) // 4224 words per buffer

__device__ float g_psums[2][CHUNKS][NUM_CLASSES][CH];
__device__ float g_pcnts[2][CHUNKS][NUM_CLASSES];
__device__ float g_csq[NUM_CLASSES];

// smem floats: tile[2][4224] | cnt[152]
#define SM_CNT      (2 * TILE_W)
#define SMEM_FLOATS (SM_CNT + 152)
#define SMEM_BYTES  (SMEM_FLOATS * 4)   // ~34.4 KB

#define ACC_CASE(k)                                                        \
    case k: acc[k].x += v0; acc[k].y += v1; acc[k].z += v2; acc[k].w += v3; break;

__global__ void __launch_bounds__(TPB, 2)
accum_kernel(const float* __restrict__ src, const float* __restrict__ trg,
             const int* __restrict__ slab, const int* __restrict__ tlab) {
    extern __shared__ float smf[];
    float* tiles = smf;                 // [2][128][33]
    int*   cnt   = (int*)(smf + SM_CNT);

    const int chunk = blockIdx.x;
    const int tsel  = blockIdx.y;
    const int chalf = blockIdx.z;
    const float* __restrict__ F =
        (tsel ? trg : src) + (size_t)chalf * HCH * NPIX;
    const int*   __restrict__ L = tsel ? tlab : slab;

    const int tid  = threadIdx.x;
    const int wid  = tid >> 5;          // owns labels lab&15 == wid
    const int lane = tid & 31;

    if (tid < NUM_CLASSES) cnt[tid] = 0;
    __syncthreads();

    const int pbase  = chunk * PPC;
    const int psz    = min(PPC, NPIX - pbase);
    const int ntiles = psz / TPX;       // 112 (last chunk: 16)

    // ---- label histogram (integer-exact, one CTA per chunk/tensor) ----
    if (chalf == 0) {
        for (int i = tid; i < psz; i += TPB)
            atomicAdd(&cnt[L[pbase + i]], 1);
    }

    // ---- register accumulators: class 16k+wid, channels lane+{0,32,64,96} ----
    float4 acc[10];
#pragma unroll
    for (int k = 0; k < 10; ++k) acc[k] = make_float4(0.f, 0.f, 0.f, 0.f);

    // ---- register prefetch of tile 0 ----
    float4 r[2];
    int mylbl;
    {
#pragma unroll
        for (int i = 0; i < 2; ++i) {
            int q = tid + TPB * i;
            int ch = q >> 3, p4 = q & 7;
            r[i] = *(const float4*)(F + (size_t)ch * NPIX + pbase + p4 * 4);
        }
        mylbl = L[pbase + lane];
    }

    for (int t = 0; t < ntiles; ++t) {
        float* tb = tiles + (t & 1) * TILE_W;

        // ---- stage: bank-perfect scalar stores ----
#pragma unroll
        for (int i = 0; i < 2; ++i) {
            int q = tid + TPB * i;
            int ch = q >> 3, p4 = q & 7;
            float* d = tb + ch * TSTRIDE + p4 * 4;
            d[0] = r[i].x; d[1] = r[i].y; d[2] = r[i].z; d[3] = r[i].w;
        }
        const int lblcur = mylbl;
        __syncthreads();   // one barrier per tile (double buffer -> safe)

        // ---- prefetch next tile ----
        if (t + 1 < ntiles) {
            const int p0 = pbase + (t + 1) * TPX;
#pragma unroll
            for (int i = 0; i < 2; ++i) {
                int q = tid + TPB * i;
                int ch = q >> 3, p4 = q & 7;
                r[i] = *(const float4*)(F + (size_t)ch * NPIX + p0 + p4 * 4);
            }
            mylbl = L[p0 + lane];
        }

        // ---- accumulate into registers: warp-uniform class switch ----
        unsigned m = __ballot_sync(0xffffffffu, (lblcur & 15) == wid);
        while (m) {
            const int j = __ffs(m) - 1;
            m &= m - 1;
            const int row = __shfl_sync(0xffffffffu, lblcur, j);
            const float* srcc = tb + lane * TSTRIDE + j;   // bank = lane+j
            const float v0 = srcc[0];
            const float v1 = srcc[32 * TSTRIDE];
            const float v2 = srcc[64 * TSTRIDE];
            const float v3 = srcc[96 * TSTRIDE];
            switch (row >> 4) {        // warp-uniform branch
                ACC_CASE(0) ACC_CASE(1) ACC_CASE(2) ACC_CASE(3) ACC_CASE(4)
                ACC_CASE(5) ACC_CASE(6) ACC_CASE(7) ACC_CASE(8) ACC_CASE(9)
            }
        }
    }
    __syncthreads();

    // ---- epilogue: registers -> partial scratch (coalesced per lane) ----
    const int nk = (wid < 6) ? 10 : 9;   // classes 16k+wid <= 149
#pragma unroll
    for (int k = 0; k < 10; ++k) {
        if (k < nk) {
            const int cls = 16 * k + wid;
            float* o = &g_psums[tsel][chunk][cls][chalf * HCH];
            o[lane]      = acc[k].x;
            o[lane + 32] = acc[k].y;
            o[lane + 64] = acc[k].z;
            o[lane + 96] = acc[k].w;
        }
    }
    if (chalf == 0 && tid < NUM_CLASSES)
        g_pcnts[tsel][chunk][tid] = (float)cnt[tid];
}

__global__ void reduce_kernel() {
    const int cidx = blockIdx.x;    // class
    const int ch   = threadIdx.x;   // channel

    float ss = 0.0f, st = 0.0f;
#pragma unroll
    for (int k = 0; k < CHUNKS; ++k) {
        ss += g_psums[0][k][cidx][ch];
        st += g_psums[1][k][cidx][ch];
    }
    float cs = 0.0f, ctn = 0.0f;
#pragma unroll
    for (int k = 0; k < CHUNKS; ++k) {
        cs  += g_pcnts[0][k][cidx];
        ctn += g_pcnts[1][k][cidx];
    }
    float d = ss / (cs + 1e-8f) - st / (ctn + 1e-8f);

    __shared__ float red[CH];
    red[ch] = d * d;
    __syncthreads();
#pragma unroll
    for (int s = CH / 2; s > 0; s >>= 1) {
        if (ch < s) red[ch] += red[ch + s];
        __syncthreads();
    }
    if (ch == 0) g_csq[cidx] = red[0];
}

__global__ void final_kernel(float* out) {
    const int l = threadIdx.x;
    float s = 0.0f;
#pragma unroll
    for (int i = l; i < NUM_CLASSES; i += 32) s += g_csq[i];
#pragma unroll
    for (int o = 16; o > 0; o >>= 1) s += __shfl_down_sync(0xffffffffu, s, o);
    if (l == 0) out[0] = sqrtf(s);
}

extern "C" void kernel_launch(void* const* d_in, const int* in_sizes, int n_in,
                              void* d_out, int out_size) {
    const float* src = (const float*)d_in[0];   // src_fea  [1,256,512,512] f32
    const float* trg = (const float*)d_in[1];   // trg_fea
    const int*   sl  = (const int*)d_in[2];     // src_labels [1,512,512] i32
    const int*   tl  = (const int*)d_in[3];     // trg_pseudo_labels
    float* out = (float*)d_out;

    cudaFuncSetAttribute(accum_kernel,
                         cudaFuncAttributeMaxDynamicSharedMemorySize,
                         SMEM_BYTES);

    dim3 grid(CHUNKS, 2, 2);   // 296 CTAs = one wave at occ 2
    accum_kernel<<<grid, TPB, SMEM_BYTES>>>(src, trg, sl, tl);
    reduce_kernel<<<NUM_CLASSES, CH>>>();
    final_kernel<<<1, 32>>>(out);
}